// round 4
// baseline (speedup 1.0000x reference)
#include <cuda_runtime.h>

// Problem constants (fixed by the reference: B=8, N=8192, D=3)
#define BATCH 8
#define NPTS 8192
#define THREADS 256
#define PTS 2                                  // adv points per thread
#define PTS_PER_BLOCK (THREADS * PTS)          // 512
#define BLOCKS_PER_BATCH (NPTS / PTS_PER_BLOCK) // 16
#define NBLOCKS (BATCH * BLOCKS_PER_BATCH)     // 128
#define TILE 1024                              // ori points staged in smem per tile

// Scratch for deterministic two-pass reduction (no device allocation allowed).
__device__ float g_partials[NBLOCKS];

// Kernel 1: for each adv point, min over all ori points of
//   v = c_o - ax*ox - ay*oy - az*oz,  where c_o = 0.5*(ox^2+oy^2+oz^2)
// Then d = r_a + 2*min(v) == ||a||^2 + ||o||^2 - 2<a,o> minimized over o.
// Writes per-block partial sums of d.
__global__ __launch_bounds__(THREADS, 1)
void chamfer_min_kernel(const float* __restrict__ adv, const float* __restrict__ ori) {
    __shared__ float4 s_tile[TILE];   // (ox, oy, oz, c_o)  16 KB
    __shared__ float  s_red[THREADS];

    const int blk  = blockIdx.x;
    const int b    = blk / BLOCKS_PER_BATCH;
    const int cblk = blk % BLOCKS_PER_BATCH;
    const int tid  = threadIdx.x;

    const float* __restrict__ advb = adv + (size_t)b * NPTS * 3;
    const float* __restrict__ orib = ori + (size_t)b * NPTS * 3;

    // Load this thread's adv points: negate coords so the inner loop is pure FFMA.
    float nax[PTS], nay[PTS], naz[PTS], ra[PTS], mn[PTS];
#pragma unroll
    for (int p = 0; p < PTS; p++) {
        const int j = cblk * PTS_PER_BLOCK + p * THREADS + tid;
        const float x = advb[j * 3 + 0];
        const float y = advb[j * 3 + 1];
        const float z = advb[j * 3 + 2];
        ra[p]  = x * x + y * y + z * z;
        nax[p] = -x; nay[p] = -y; naz[p] = -z;
        mn[p]  = __int_as_float(0x7f800000);  // +inf
    }

    for (int t0 = 0; t0 < NPTS; t0 += TILE) {
        // Stage ori tile into smem with the half-squared-norm folded in.
        for (int i = tid; i < TILE; i += THREADS) {
            const float x = orib[(t0 + i) * 3 + 0];
            const float y = orib[(t0 + i) * 3 + 1];
            const float z = orib[(t0 + i) * 3 + 2];
            s_tile[i] = make_float4(x, y, z, 0.5f * (x * x + y * y + z * z));
        }
        __syncthreads();

#pragma unroll 8
        for (int i = 0; i < TILE; i++) {
            const float4 o = s_tile[i];   // broadcast LDS.128 (conflict-free)
#pragma unroll
            for (int p = 0; p < PTS; p++) {
                // 3 FFMA per pair (fma pipe) + 1 FMNMX (alu pipe)
                const float v = fmaf(nax[p], o.x,
                                 fmaf(nay[p], o.y,
                                  fmaf(naz[p], o.z, o.w)));
                mn[p] = fminf(mn[p], v);
            }
        }
        __syncthreads();
    }

    // Per-thread sum of nearest distances, then block reduction.
    float sum = 0.0f;
#pragma unroll
    for (int p = 0; p < PTS; p++) sum += ra[p] + 2.0f * mn[p];

    s_red[tid] = sum;
    __syncthreads();
    for (int s2 = THREADS / 2; s2 > 32; s2 >>= 1) {
        if (tid < s2) s_red[tid] += s_red[tid + s2];
        __syncthreads();
    }
    if (tid < 32) {
        float v = s_red[tid] + s_red[tid + 32];
#pragma unroll
        for (int o = 16; o > 0; o >>= 1)
            v += __shfl_down_sync(0xffffffffu, v, o);
        if (tid == 0) g_partials[blk] = v;
    }
}

// Kernel 2: weighted mean over the 128 partials (deterministic).
// out = (1/B) * sum_b weights[b] * (1/N) * sum_j d_{b,j}
__global__ void chamfer_finalize_kernel(const float* __restrict__ weights,
                                        float* __restrict__ out) {
    __shared__ float s_red[NBLOCKS];
    const int tid = threadIdx.x;   // NBLOCKS threads
    const int b = tid / BLOCKS_PER_BATCH;
    float v = g_partials[tid] * weights[b];
    s_red[tid] = v;
    __syncthreads();
    for (int s2 = NBLOCKS / 2; s2 > 32; s2 >>= 1) {
        if (tid < s2) s_red[tid] += s_red[tid + s2];
        __syncthreads();
    }
    if (tid < 32) {
        float w = s_red[tid] + s_red[tid + 32];
#pragma unroll
        for (int o = 16; o > 0; o >>= 1)
            w += __shfl_down_sync(0xffffffffu, w, o);
        if (tid == 0)
            out[0] = w * (1.0f / ((float)NPTS * (float)BATCH));
    }
}

extern "C" void kernel_launch(void* const* d_in, const int* in_sizes, int n_in,
                              void* d_out, int out_size) {
    const float* adv     = (const float*)d_in[0];  // adv_pc  [B, N, 3]
    const float* ori     = (const float*)d_in[1];  // ori_pc  [B, N, 3]
    const float* weights = (const float*)d_in[2];  // weights [B]
    float* out = (float*)d_out;                    // scalar

    chamfer_min_kernel<<<NBLOCKS, THREADS>>>(adv, ori);
    chamfer_finalize_kernel<<<1, NBLOCKS>>>(weights, out);
}